// round 14
// baseline (speedup 1.0000x reference)
#include <cuda_runtime.h>
#include <cstdint>
#include <cstddef>

// Problem dims
#define BB 16
#define TT 4096
#define DD 512
#define HH 512
#define NC 1536   // 3*H

typedef unsigned long long ull;

// ---------------- scratch (device globals: no runtime allocation allowed) ---
__device__ float g_xk[(size_t)BB * TT * NC];   // 402 MB: x @ kernel + bias0
__device__ float g_hbuf[2][BB][HH];            // double-buffered hidden state
__device__ int   g_ctr[8 * TT];                // per-group per-step arrivals

// ---------------- f32x2 packed-math helpers (sm_103a) -----------------------
__device__ __forceinline__ ull pk2(float lo, float hi) {
    ull r;
    asm("mov.b64 %0, {%1, %2};" : "=l"(r) : "f"(lo), "f"(hi));
    return r;
}
__device__ __forceinline__ void unpk2(float& lo, float& hi, ull v) {
    asm("mov.b64 {%0, %1}, %2;" : "=f"(lo), "=f"(hi) : "l"(v));
}
__device__ __forceinline__ ull fma2(ull a, ull b, ull c) {
    ull d;
    asm("fma.rn.f32x2 %0, %1, %2, %3;" : "=l"(d) : "l"(a), "l"(b), "l"(c));
    return d;
}
__device__ __forceinline__ float sigmoid_f(float x) {
    return 1.f / (1.f + __expf(-x));
}
__device__ __forceinline__ float tanh_f(float x) {
    float e = __expf(2.f * x);
    return (e - 1.f) / (e + 1.f);
}
__device__ __forceinline__ uint32_t f2tf32(float f) {
    uint32_t r;
    asm("cvt.rna.tf32.f32 %0, %1;" : "=r"(r) : "f"(f));
    return r;
}
__device__ __forceinline__ void mma_tf32(float* c,
                                         uint32_t a0, uint32_t a1,
                                         uint32_t a2, uint32_t a3,
                                         uint32_t b0, uint32_t b1) {
    asm volatile(
        "mma.sync.aligned.m16n8k8.row.col.f32.tf32.tf32.f32 "
        "{%0,%1,%2,%3}, {%4,%5,%6,%7}, {%8,%9}, {%0,%1,%2,%3};"
        : "+f"(c[0]), "+f"(c[1]), "+f"(c[2]), "+f"(c[3])
        : "r"(a0), "r"(a1), "r"(a2), "r"(a3), "r"(b0), "r"(b1));
}

// ============================================================================
// Phase 1: xk = x @ W + bias0  (tf32 tensor cores, unchanged from R12)
// ============================================================================
#define GBM 128
#define GBN 64
#define GBK 32
#define ASTR 36
#define BSTR 68

__global__ void __launch_bounds__(256, 2)
gemm_xk_tf32(const float* __restrict__ A,
             const float* __restrict__ W,
             const float* __restrict__ bias)
{
    __shared__ float As[2][GBM][ASTR];
    __shared__ float Bs[2][GBK][BSTR];

    const int bm   = blockIdx.y * GBM;
    const int bn   = blockIdx.x * GBN;
    const int tid  = threadIdx.x;
    const int wid  = tid >> 5;
    const int lane = tid & 31;
    const int wm   = (wid & 3) * 32;
    const int wn   = (wid >> 2) * 32;
    const int lr   = lane >> 2;
    const int lc   = lane & 3;

    float acc[2][4][4];
#pragma unroll
    for (int mi = 0; mi < 2; mi++)
#pragma unroll
        for (int ni = 0; ni < 4; ni++)
#pragma unroll
            for (int q = 0; q < 4; q++) acc[mi][ni][q] = 0.f;

    float4 aref[4], bref[2];

#pragma unroll
    for (int i = 0; i < 4; i++) {
        int f = tid + i * 256, row = f >> 3, c4 = (f & 7) << 2;
        aref[i] = *(const float4*)&A[(size_t)(bm + row) * DD + c4];
    }
#pragma unroll
    for (int i = 0; i < 2; i++) {
        int f = tid + i * 256, k = f >> 4, n4 = (f & 15) << 2;
        bref[i] = *(const float4*)&W[(size_t)k * NC + bn + n4];
    }
#pragma unroll
    for (int i = 0; i < 4; i++) {
        int f = tid + i * 256, row = f >> 3, c4 = (f & 7) << 2;
        *(float4*)&As[0][row][c4] = aref[i];
    }
#pragma unroll
    for (int i = 0; i < 2; i++) {
        int f = tid + i * 256, k = f >> 4, n4 = (f & 15) << 2;
        *(float4*)&Bs[0][k][n4] = bref[i];
    }
    __syncthreads();

    const int NKT = DD / GBK;
    for (int kt = 0; kt < NKT; kt++) {
        const int cur = kt & 1;

        if (kt < NKT - 1) {
            int kb = (kt + 1) * GBK;
#pragma unroll
            for (int i = 0; i < 4; i++) {
                int f = tid + i * 256, row = f >> 3, c4 = (f & 7) << 2;
                aref[i] = *(const float4*)&A[(size_t)(bm + row) * DD + kb + c4];
            }
#pragma unroll
            for (int i = 0; i < 2; i++) {
                int f = tid + i * 256, k = f >> 4, n4 = (f & 15) << 2;
                bref[i] = *(const float4*)&W[(size_t)(kb + k) * NC + bn + n4];
            }
        }

#pragma unroll
        for (int k8 = 0; k8 < 4; k8++) {
            uint32_t bf[4][2];
#pragma unroll
            for (int ni = 0; ni < 4; ni++) {
                int cb = wn + ni * 8;
                bf[ni][0] = f2tf32(Bs[cur][k8 * 8 + lc    ][cb + lr]);
                bf[ni][1] = f2tf32(Bs[cur][k8 * 8 + lc + 4][cb + lr]);
            }
#pragma unroll
            for (int mi = 0; mi < 2; mi++) {
                int rb = wm + mi * 16;
                uint32_t a0 = f2tf32(As[cur][rb + lr    ][k8 * 8 + lc    ]);
                uint32_t a1 = f2tf32(As[cur][rb + lr + 8][k8 * 8 + lc    ]);
                uint32_t a2 = f2tf32(As[cur][rb + lr    ][k8 * 8 + lc + 4]);
                uint32_t a3 = f2tf32(As[cur][rb + lr + 8][k8 * 8 + lc + 4]);
#pragma unroll
                for (int ni = 0; ni < 4; ni++)
                    mma_tf32(acc[mi][ni], a0, a1, a2, a3, bf[ni][0], bf[ni][1]);
            }
        }

        if (kt < NKT - 1) {
            __syncthreads();
#pragma unroll
            for (int i = 0; i < 4; i++) {
                int f = tid + i * 256, row = f >> 3, c4 = (f & 7) << 2;
                *(float4*)&As[cur ^ 1][row][c4] = aref[i];
            }
#pragma unroll
            for (int i = 0; i < 2; i++) {
                int f = tid + i * 256, k = f >> 4, n4 = (f & 15) << 2;
                *(float4*)&Bs[cur ^ 1][k][n4] = bref[i];
            }
            __syncthreads();
        }
    }

#pragma unroll
    for (int mi = 0; mi < 2; mi++) {
#pragma unroll
        for (int ni = 0; ni < 4; ni++) {
            int r0 = bm + wm + mi * 16 + lr;
            int c0 = bn + wn + ni * 8 + lc * 2;
            float bz0 = bias[c0], bz1 = bias[c0 + 1];
            float2 v0 = make_float2(acc[mi][ni][0] + bz0, acc[mi][ni][1] + bz1);
            float2 v1 = make_float2(acc[mi][ni][2] + bz0, acc[mi][ni][3] + bz1);
            *(float2*)&g_xk[(size_t)r0 * NC + c0]       = v0;
            *(float2*)&g_xk[(size_t)(r0 + 8) * NC + c0] = v1;
        }
    }
}

// ============================================================================
// Phase 2: persistent GRU recurrence — R12 structure + POLL DELEGATION.
//   8 groups x 16 CTAs; CTA c owns units [32c,32c+32); thread (u=lane,
//   ks=warp) holds U[k0..k0+32) for unit u's 3 gate columns (48 f32x2 regs).
//   Per step:
//     dot -> red[] -> __syncthreads
//     gate warps (ks<2): 16-way reduce, gates, STG h' to g_hbuf[par^1],
//       __syncwarp, lane0 red.release.gpu ctr[t]
//     ONLY warp 15 lane 0 polls ctr[t]==32 (16 pollers/line instead of 256,
//       no h-load spam during the wait) then writes monotonic smem flag t+1.
//     All warps spin on the smem flag (LDS, no L2 traffic), then load their
//       own h chunk (ld.cg — L2 is the point of coherence; producers'
//       release-RED ordered their stores before the counter), STS, syncwarp.
// ============================================================================
__global__ void __launch_bounds__(512, 1)
gru_rec_kernel(const float* __restrict__ RK,
               const float* __restrict__ bias,
               float* __restrict__ out)
{
    __shared__ float red[16][32][7];       // [ks][u][gate*2+b]
    __shared__ float h_chunk[16][2][32];   // per-warp private h slice
    __shared__ float rb_s[96];             // recurrent bias slice
    __shared__ volatile int sflag;         // monotonic step flag

    const int bx  = blockIdx.x;
    const int g   = bx >> 4;               // group 0..7
    const int c   = bx & 15;               // cta-in-group 0..15
    const int tid = threadIdx.x;
    const int u   = tid & 31;              // lane
    const int ks  = tid >> 5;              // warp / K-split 0..15
    const int jb  = c * 32;                // first unit owned
    const int b0  = g * 2;                 // first global batch
    const int k0  = ks * 32;               // this warp's K chunk

    // ---- Load U slice into registers ---------------------------------------
    ull ureg[3][16];
#pragma unroll
    for (int gi = 0; gi < 3; gi++)
#pragma unroll
        for (int i = 0; i < 16; i++) {
            int k = k0 + 2 * i;
            float lo = RK[(size_t)k       * NC + gi * HH + jb + u];
            float hi = RK[(size_t)(k + 1) * NC + gi * HH + jb + u];
            ureg[gi][i] = pk2(lo, hi);
        }
    if (tid < 96)
        rb_s[tid] = bias[NC + (tid >> 5) * HH + jb + (tid & 31)];
    // zero own h chunk (h0 = 0)
    for (int i = u; i < 64; i += 32) ((float*)h_chunk[ks])[i] = 0.f;
    if (tid == 0) sflag = 0;
    __syncthreads();

    int* ctr = &g_ctr[g * TT];

    // reload-phase lane mapping: lane -> (batch, pair-index)
    const int rl_b = u >> 4;               // 0..1
    const int rl_l = u & 15;               // 0..15

    float h_old = 0.f;                     // gate threads: own h from last step

    // xk prefetch for t = 0 (gate warps only)
    float xz = 0.f, xr = 0.f, xh = 0.f;
    size_t xbase0 = 0;
    if (ks < 2) {
        xbase0 = ((size_t)(b0 + ks) * TT) * NC + jb + u;
        xz = g_xk[xbase0];
        xr = g_xk[xbase0 + HH];
        xh = g_xk[xbase0 + 2 * HH];
    }

    for (int t = 0; t < TT; t++) {
        // ---- packed dot over own 32-wide K chunk ---------------------------
        const ull* hp0 = (const ull*)h_chunk[ks][0];
        const ull* hp1 = (const ull*)h_chunk[ks][1];
        ull a0 = 0, a1 = 0, a2 = 0, a3 = 0, a4 = 0, a5 = 0;
#pragma unroll
        for (int i = 0; i < 16; i++) {
            ull h0 = hp0[i];               // broadcast LDS.64
            ull h1 = hp1[i];
            a0 = fma2(ureg[0][i], h0, a0);
            a1 = fma2(ureg[1][i], h0, a1);
            a2 = fma2(ureg[2][i], h0, a2);
            a3 = fma2(ureg[0][i], h1, a3);
            a4 = fma2(ureg[1][i], h1, a4);
            a5 = fma2(ureg[2][i], h1, a5);
        }
        {
            float lo, hi;
            unpk2(lo, hi, a0); red[ks][u][0] = lo + hi;   // z, b0
            unpk2(lo, hi, a1); red[ks][u][2] = lo + hi;   // r, b0
            unpk2(lo, hi, a2); red[ks][u][4] = lo + hi;   // h, b0
            unpk2(lo, hi, a3); red[ks][u][1] = lo + hi;   // z, b1
            unpk2(lo, hi, a4); red[ks][u][3] = lo + hi;   // r, b1
            unpk2(lo, hi, a5); red[ks][u][5] = lo + hi;   // h, b1
        }
        __syncthreads();

        // ---- gate warps: reduce + gates + publish + release-signal ---------
        if (ks < 2) {
            float s0 = 0.f, s1 = 0.f, s2 = 0.f;
#pragma unroll
            for (int q = 0; q < 16; q++) {
                s0 += red[q][u][0 + ks];
                s1 += red[q][u][2 + ks];
                s2 += red[q][u][4 + ks];
            }
            s0 += rb_s[u];
            s1 += rb_s[32 + u];
            s2 += rb_s[64 + u];

            float z    = sigmoid_f(xz + s0);
            float r    = sigmoid_f(xr + s1);
            float cand = tanh_f(xh + r * s2);
            float hn   = z * h_old + (1.f - z) * cand;
            h_old = hn;

            int gb = b0 + ks;
            out[((size_t)gb * TT + t) * HH + jb + u] = hn;
            if (t == TT - 1)
                out[(size_t)BB * TT * HH + (size_t)gb * HH + jb + u] = hn;
            asm volatile("st.global.cg.f32 [%0], %1;"
                         :: "l"(&g_hbuf[(t + 1) & 1][gb][jb + u]), "f"(hn)
                         : "memory");

            // prefetch next step's xk (consumed next iteration)
            {
                size_t nb = xbase0 + (size_t)((t + 1 < TT) ? t + 1 : t) * NC;
                xz = g_xk[nb];
                xr = g_xk[nb + HH];
                xh = g_xk[nb + 2 * HH];
            }

            __syncwarp();                  // warp stores HB-before lane0's RED
            if (u == 0)
                asm volatile("red.release.gpu.global.add.s32 [%0], %1;"
                             :: "l"(&ctr[t]), "r"(1) : "memory");
        }

        // ---- delegated poll: warp 15 lane 0 only ---------------------------
        if (ks == 15 && u == 0) {
            int cv;
            do {
                asm volatile("ld.acquire.gpu.global.b32 %0, [%1];"
                             : "=r"(cv) : "l"(&ctr[t]) : "memory");
            } while (cv != 32);
            sflag = t + 1;                 // monotonic smem broadcast
        }
        // all warps: cheap LDS spin (no L2 traffic)
        while (sflag != t + 1) { }

        // ---- own-chunk reload (L2 holds committed h'; .cg skips L1) --------
        {
            const float* src = &g_hbuf[(t + 1) & 1][b0 + rl_b][k0 + 2 * rl_l];
            ull v;
            asm volatile("ld.global.cg.b64 %0, [%1];"
                         : "=l"(v) : "l"(src) : "memory");
            *(ull*)&h_chunk[ks][rl_b][2 * rl_l] = v;
        }
        __syncwarp();
    }
}

// ============================================================================
extern "C" void kernel_launch(void* const* d_in, const int* in_sizes, int n_in,
                              void* d_out, int out_size)
{
    const float* x    = (const float*)d_in[0];   // [16,4096,512]
    const float* Wk   = (const float*)d_in[1];   // [512,1536]
    const float* RK   = (const float*)d_in[2];   // [512,1536]
    const float* bias = (const float*)d_in[3];   // [2,1536]
    float* out = (float*)d_out;                  // outputs ++ state

    // Zero the arrival counters (memset node; re-zeroed per graph replay).
    void* ctr_ptr = nullptr;
    cudaGetSymbolAddress(&ctr_ptr, g_ctr);
    cudaMemsetAsync(ctr_ptr, 0, sizeof(int) * 8 * TT);

    // Phase 1: input projection GEMM (tf32 tensor cores).
    dim3 grid1(NC / GBN, (BB * TT) / GBM);
    gemm_xk_tf32<<<grid1, 256>>>(x, Wk, bias);

    // Phase 2: persistent recurrence (delegated poll).
    gru_rec_kernel<<<128, 512>>>(RK, bias, out);
}

// round 15
// speedup vs baseline: 1.6785x; 1.6785x over previous
#include <cuda_runtime.h>
#include <cstdint>
#include <cstddef>

// Problem dims
#define BB 16
#define TT 4096
#define DD 512
#define HH 512
#define NC 1536   // 3*H

typedef unsigned long long ull;

// ---------------- scratch (device globals: no runtime allocation allowed) ---
__device__ float g_xk[(size_t)BB * TT * NC];   // 402 MB: x @ kernel + bias0
__device__ float g_hbuf[2][BB][HH];            // double-buffered hidden state
__device__ int   g_ctr[8 * TT * 16];           // [group][t][srcCTA] arrivals (2MB)

// ---------------- f32x2 packed-math helpers (sm_103a) -----------------------
__device__ __forceinline__ ull pk2(float lo, float hi) {
    ull r;
    asm("mov.b64 %0, {%1, %2};" : "=l"(r) : "f"(lo), "f"(hi));
    return r;
}
__device__ __forceinline__ void unpk2(float& lo, float& hi, ull v) {
    asm("mov.b64 {%0, %1}, %2;" : "=f"(lo), "=f"(hi) : "l"(v));
}
__device__ __forceinline__ ull fma2(ull a, ull b, ull c) {
    ull d;
    asm("fma.rn.f32x2 %0, %1, %2, %3;" : "=l"(d) : "l"(a), "l"(b), "l"(c));
    return d;
}
__device__ __forceinline__ float sigmoid_f(float x) {
    return 1.f / (1.f + __expf(-x));
}
__device__ __forceinline__ float tanh_f(float x) {
    float e = __expf(2.f * x);
    return (e - 1.f) / (e + 1.f);
}
__device__ __forceinline__ uint32_t f2tf32(float f) {
    uint32_t r;
    asm("cvt.rna.tf32.f32 %0, %1;" : "=r"(r) : "f"(f));
    return r;
}
__device__ __forceinline__ void mma_tf32(float* c,
                                         uint32_t a0, uint32_t a1,
                                         uint32_t a2, uint32_t a3,
                                         uint32_t b0, uint32_t b1) {
    asm volatile(
        "mma.sync.aligned.m16n8k8.row.col.f32.tf32.tf32.f32 "
        "{%0,%1,%2,%3}, {%4,%5,%6,%7}, {%8,%9}, {%0,%1,%2,%3};"
        : "+f"(c[0]), "+f"(c[1]), "+f"(c[2]), "+f"(c[3])
        : "r"(a0), "r"(a1), "r"(a2), "r"(a3), "r"(b0), "r"(b1));
}

// ============================================================================
// Phase 1: xk = x @ W + bias0  (tf32 tensor cores, unchanged from R12)
// ============================================================================
#define GBM 128
#define GBN 64
#define GBK 32
#define ASTR 36
#define BSTR 68

__global__ void __launch_bounds__(256, 2)
gemm_xk_tf32(const float* __restrict__ A,
             const float* __restrict__ W,
             const float* __restrict__ bias)
{
    __shared__ float As[2][GBM][ASTR];
    __shared__ float Bs[2][GBK][BSTR];

    const int bm   = blockIdx.y * GBM;
    const int bn   = blockIdx.x * GBN;
    const int tid  = threadIdx.x;
    const int wid  = tid >> 5;
    const int lane = tid & 31;
    const int wm   = (wid & 3) * 32;
    const int wn   = (wid >> 2) * 32;
    const int lr   = lane >> 2;
    const int lc   = lane & 3;

    float acc[2][4][4];
#pragma unroll
    for (int mi = 0; mi < 2; mi++)
#pragma unroll
        for (int ni = 0; ni < 4; ni++)
#pragma unroll
            for (int q = 0; q < 4; q++) acc[mi][ni][q] = 0.f;

    float4 aref[4], bref[2];

#pragma unroll
    for (int i = 0; i < 4; i++) {
        int f = tid + i * 256, row = f >> 3, c4 = (f & 7) << 2;
        aref[i] = *(const float4*)&A[(size_t)(bm + row) * DD + c4];
    }
#pragma unroll
    for (int i = 0; i < 2; i++) {
        int f = tid + i * 256, k = f >> 4, n4 = (f & 15) << 2;
        bref[i] = *(const float4*)&W[(size_t)k * NC + bn + n4];
    }
#pragma unroll
    for (int i = 0; i < 4; i++) {
        int f = tid + i * 256, row = f >> 3, c4 = (f & 7) << 2;
        *(float4*)&As[0][row][c4] = aref[i];
    }
#pragma unroll
    for (int i = 0; i < 2; i++) {
        int f = tid + i * 256, k = f >> 4, n4 = (f & 15) << 2;
        *(float4*)&Bs[0][k][n4] = bref[i];
    }
    __syncthreads();

    const int NKT = DD / GBK;
    for (int kt = 0; kt < NKT; kt++) {
        const int cur = kt & 1;

        if (kt < NKT - 1) {
            int kb = (kt + 1) * GBK;
#pragma unroll
            for (int i = 0; i < 4; i++) {
                int f = tid + i * 256, row = f >> 3, c4 = (f & 7) << 2;
                aref[i] = *(const float4*)&A[(size_t)(bm + row) * DD + kb + c4];
            }
#pragma unroll
            for (int i = 0; i < 2; i++) {
                int f = tid + i * 256, k = f >> 4, n4 = (f & 15) << 2;
                bref[i] = *(const float4*)&W[(size_t)(kb + k) * NC + bn + n4];
            }
        }

#pragma unroll
        for (int k8 = 0; k8 < 4; k8++) {
            uint32_t bf[4][2];
#pragma unroll
            for (int ni = 0; ni < 4; ni++) {
                int cb = wn + ni * 8;
                bf[ni][0] = f2tf32(Bs[cur][k8 * 8 + lc    ][cb + lr]);
                bf[ni][1] = f2tf32(Bs[cur][k8 * 8 + lc + 4][cb + lr]);
            }
#pragma unroll
            for (int mi = 0; mi < 2; mi++) {
                int rb = wm + mi * 16;
                uint32_t a0 = f2tf32(As[cur][rb + lr    ][k8 * 8 + lc    ]);
                uint32_t a1 = f2tf32(As[cur][rb + lr + 8][k8 * 8 + lc    ]);
                uint32_t a2 = f2tf32(As[cur][rb + lr    ][k8 * 8 + lc + 4]);
                uint32_t a3 = f2tf32(As[cur][rb + lr + 8][k8 * 8 + lc + 4]);
#pragma unroll
                for (int ni = 0; ni < 4; ni++)
                    mma_tf32(acc[mi][ni], a0, a1, a2, a3, bf[ni][0], bf[ni][1]);
            }
        }

        if (kt < NKT - 1) {
            __syncthreads();
#pragma unroll
            for (int i = 0; i < 4; i++) {
                int f = tid + i * 256, row = f >> 3, c4 = (f & 7) << 2;
                *(float4*)&As[cur ^ 1][row][c4] = aref[i];
            }
#pragma unroll
            for (int i = 0; i < 2; i++) {
                int f = tid + i * 256, k = f >> 4, n4 = (f & 15) << 2;
                *(float4*)&Bs[cur ^ 1][k][n4] = bref[i];
            }
            __syncthreads();
        }
    }

#pragma unroll
    for (int mi = 0; mi < 2; mi++) {
#pragma unroll
        for (int ni = 0; ni < 4; ni++) {
            int r0 = bm + wm + mi * 16 + lr;
            int c0 = bn + wn + ni * 8 + lc * 2;
            float bz0 = bias[c0], bz1 = bias[c0 + 1];
            float2 v0 = make_float2(acc[mi][ni][0] + bz0, acc[mi][ni][1] + bz1);
            float2 v1 = make_float2(acc[mi][ni][2] + bz0, acc[mi][ni][3] + bz1);
            *(float2*)&g_xk[(size_t)r0 * NC + c0]       = v0;
            *(float2*)&g_xk[(size_t)(r0 + 8) * NC + c0] = v1;
        }
    }
}

// ============================================================================
// Phase 2: persistent GRU recurrence — PER-SOURCE counters (wavefront sync).
//   8 groups x 16 CTAs; CTA c owns units [32c,32c+32); thread (u=lane,
//   ks=warp) holds U[k0..k0+32) for unit u's 3 gate columns (48 f32x2 regs).
//   Sync: ctr[g][t][src], target 2 (src CTA's 2 gate warps release it after
//   storing their h' slice). Warp ks consumes ONLY CTA ks's 64 h-values, so
//   it fused-polls ctr[g][t][ks] and reloads early — fast sources' warps
//   re-issue their dots while slow sources finish, taking the 768-cyc FMA
//   issue block off the critical path.
//   red[] is parity double-buffered: warps racing ahead write red[par^1] and
//   then block at the next __syncthreads until the gate warps (still reading
//   red[par]) arrive. h ping-pong safety: publish(t+1) transitively requires
//   every warp everywhere passed poll(t-1), i.e. finished reading h(t-1).
// ============================================================================
__global__ void __launch_bounds__(512, 1)
gru_rec_kernel(const float* __restrict__ RK,
               const float* __restrict__ bias,
               float* __restrict__ out)
{
    __shared__ float red[2][16][32][7];    // [parity][ks][u][gate*2+b]
    __shared__ float h_chunk[16][2][32];   // per-warp private h slice
    __shared__ float rb_s[96];             // recurrent bias slice

    const int bx  = blockIdx.x;
    const int g   = bx >> 4;               // group 0..7
    const int c   = bx & 15;               // cta-in-group 0..15
    const int tid = threadIdx.x;
    const int u   = tid & 31;              // lane
    const int ks  = tid >> 5;              // warp / K-split 0..15
    const int jb  = c * 32;                // first unit owned
    const int b0  = g * 2;                 // first global batch
    const int k0  = ks * 32;               // this warp's K chunk

    // ---- Load U slice into registers ---------------------------------------
    ull ureg[3][16];
#pragma unroll
    for (int gi = 0; gi < 3; gi++)
#pragma unroll
        for (int i = 0; i < 16; i++) {
            int k = k0 + 2 * i;
            float lo = RK[(size_t)k       * NC + gi * HH + jb + u];
            float hi = RK[(size_t)(k + 1) * NC + gi * HH + jb + u];
            ureg[gi][i] = pk2(lo, hi);
        }
    if (tid < 96)
        rb_s[tid] = bias[NC + (tid >> 5) * HH + jb + (tid & 31)];
    // zero own h chunk (h0 = 0)
    for (int i = u; i < 64; i += 32) ((float*)h_chunk[ks])[i] = 0.f;
    __syncthreads();

    int* ctr_base = &g_ctr[(size_t)g * TT * 16];

    // reload-phase lane mapping: lane -> (batch, pair-index)
    const int rl_b = u >> 4;               // 0..1
    const int rl_l = u & 15;               // 0..15

    float h_old = 0.f;                     // gate threads: own h from last step

    // xk prefetch for t = 0 (gate warps only)
    float xz = 0.f, xr = 0.f, xh = 0.f;
    size_t xbase0 = 0;
    if (ks < 2) {
        xbase0 = ((size_t)(b0 + ks) * TT) * NC + jb + u;
        xz = g_xk[xbase0];
        xr = g_xk[xbase0 + HH];
        xh = g_xk[xbase0 + 2 * HH];
    }

    for (int t = 0; t < TT; t++) {
        const int par = t & 1;

        // ---- packed dot over own 32-wide K chunk ---------------------------
        const ull* hp0 = (const ull*)h_chunk[ks][0];
        const ull* hp1 = (const ull*)h_chunk[ks][1];
        ull a0 = 0, a1 = 0, a2 = 0, a3 = 0, a4 = 0, a5 = 0;
#pragma unroll
        for (int i = 0; i < 16; i++) {
            ull h0 = hp0[i];               // broadcast LDS.64
            ull h1 = hp1[i];
            a0 = fma2(ureg[0][i], h0, a0);
            a1 = fma2(ureg[1][i], h0, a1);
            a2 = fma2(ureg[2][i], h0, a2);
            a3 = fma2(ureg[0][i], h1, a3);
            a4 = fma2(ureg[1][i], h1, a4);
            a5 = fma2(ureg[2][i], h1, a5);
        }
        {
            float lo, hi;
            unpk2(lo, hi, a0); red[par][ks][u][0] = lo + hi;   // z, b0
            unpk2(lo, hi, a1); red[par][ks][u][2] = lo + hi;   // r, b0
            unpk2(lo, hi, a2); red[par][ks][u][4] = lo + hi;   // h, b0
            unpk2(lo, hi, a3); red[par][ks][u][1] = lo + hi;   // z, b1
            unpk2(lo, hi, a4); red[par][ks][u][3] = lo + hi;   // r, b1
            unpk2(lo, hi, a5); red[par][ks][u][5] = lo + hi;   // h, b1
        }
        __syncthreads();

        // ---- gate warps: reduce + gates + publish + per-src release --------
        if (ks < 2) {
            float s0 = 0.f, s1 = 0.f, s2 = 0.f;
#pragma unroll
            for (int q = 0; q < 16; q++) {
                s0 += red[par][q][u][0 + ks];
                s1 += red[par][q][u][2 + ks];
                s2 += red[par][q][u][4 + ks];
            }
            s0 += rb_s[u];
            s1 += rb_s[32 + u];
            s2 += rb_s[64 + u];

            float z    = sigmoid_f(xz + s0);
            float r    = sigmoid_f(xr + s1);
            float cand = tanh_f(xh + r * s2);
            float hn   = z * h_old + (1.f - z) * cand;
            h_old = hn;

            int gb = b0 + ks;
            out[((size_t)gb * TT + t) * HH + jb + u] = hn;
            if (t == TT - 1)
                out[(size_t)BB * TT * HH + (size_t)gb * HH + jb + u] = hn;
            asm volatile("st.global.cg.f32 [%0], %1;"
                         :: "l"(&g_hbuf[(t + 1) & 1][gb][jb + u]), "f"(hn)
                         : "memory");

            // prefetch next step's xk (consumed next iteration)
            {
                size_t nb = xbase0 + (size_t)((t + 1 < TT) ? t + 1 : t) * NC;
                xz = g_xk[nb];
                xr = g_xk[nb + HH];
                xh = g_xk[nb + 2 * HH];
            }

            __syncwarp();                  // warp stores HB-before lane0's RED
            if (u == 0)
                asm volatile("red.release.gpu.global.add.s32 [%0], %1;"
                             :: "l"(ctr_base + t * 16 + c), "r"(1) : "memory");
        }

        // ---- fused acquire-poll on OWN SOURCE + chunk reload ---------------
        {
            const int*   myctr = ctr_base + t * 16 + ks;
            const float* src   = &g_hbuf[(t + 1) & 1][b0 + rl_b][k0 + 2 * rl_l];
            int cv;
            ull v;
            do {
                asm volatile("ld.acquire.gpu.global.b32 %0, [%1];"
                             : "=r"(cv) : "l"(myctr) : "memory");
                asm volatile("ld.global.cg.b64 %0, [%1];"
                             : "=l"(v) : "l"(src) : "memory");
            } while (cv != 2);
            // loop exits => the b64 load above was issued after a successful
            // acquire of ctr==2 (both producer warps released), so v is the
            // committed h' value for this warp's chunk.
            *(ull*)&h_chunk[ks][rl_b][2 * rl_l] = v;
        }
        __syncwarp();
    }
}

// ============================================================================
extern "C" void kernel_launch(void* const* d_in, const int* in_sizes, int n_in,
                              void* d_out, int out_size)
{
    const float* x    = (const float*)d_in[0];   // [16,4096,512]
    const float* Wk   = (const float*)d_in[1];   // [512,1536]
    const float* RK   = (const float*)d_in[2];   // [512,1536]
    const float* bias = (const float*)d_in[3];   // [2,1536]
    float* out = (float*)d_out;                  // outputs ++ state

    // Zero the per-source arrival counters (memset node; re-zeroed per replay).
    void* ctr_ptr = nullptr;
    cudaGetSymbolAddress(&ctr_ptr, g_ctr);
    cudaMemsetAsync(ctr_ptr, 0, sizeof(int) * 8 * TT * 16);

    // Phase 1: input projection GEMM (tf32 tensor cores).
    dim3 grid1(NC / GBN, (BB * TT) / GBM);
    gemm_xk_tf32<<<grid1, 256>>>(x, Wk, bias);

    // Phase 2: persistent recurrence (per-source counters).
    gru_rec_kernel<<<128, 512>>>(RK, bias, out);
}

// round 16
// speedup vs baseline: 2.6285x; 1.5660x over previous
#include <cuda_runtime.h>
#include <cstdint>
#include <cstddef>

// Problem dims
#define BB 16
#define TT 4096
#define DD 512
#define HH 512
#define NC 1536   // 3*H

typedef unsigned long long ull;

// ---------------- scratch (device globals: no runtime allocation allowed) ---
__device__ float g_xk[(size_t)BB * TT * NC];   // 402 MB: x @ kernel + bias0
__device__ ull   g_hx[2][BB][HH];              // 128 KB: tagged {h, step} words

// ---------------- f32x2 packed-math helpers (sm_103a) -----------------------
__device__ __forceinline__ ull pk2(float lo, float hi) {
    ull r;
    asm("mov.b64 %0, {%1, %2};" : "=l"(r) : "f"(lo), "f"(hi));
    return r;
}
__device__ __forceinline__ void unpk2(float& lo, float& hi, ull v) {
    asm("mov.b64 {%0, %1}, %2;" : "=f"(lo), "=f"(hi) : "l"(v));
}
__device__ __forceinline__ ull fma2(ull a, ull b, ull c) {
    ull d;
    asm("fma.rn.f32x2 %0, %1, %2, %3;" : "=l"(d) : "l"(a), "l"(b), "l"(c));
    return d;
}
__device__ __forceinline__ float sigmoid_f(float x) {
    return 1.f / (1.f + __expf(-x));
}
__device__ __forceinline__ float tanh_f(float x) {
    float e = __expf(2.f * x);
    return (e - 1.f) / (e + 1.f);
}
__device__ __forceinline__ uint32_t f2tf32(float f) {
    uint32_t r;
    asm("cvt.rna.tf32.f32 %0, %1;" : "=r"(r) : "f"(f));
    return r;
}
__device__ __forceinline__ void mma_tf32(float* c,
                                         uint32_t a0, uint32_t a1,
                                         uint32_t a2, uint32_t a3,
                                         uint32_t b0, uint32_t b1) {
    asm volatile(
        "mma.sync.aligned.m16n8k8.row.col.f32.tf32.tf32.f32 "
        "{%0,%1,%2,%3}, {%4,%5,%6,%7}, {%8,%9}, {%0,%1,%2,%3};"
        : "+f"(c[0]), "+f"(c[1]), "+f"(c[2]), "+f"(c[3])
        : "r"(a0), "r"(a1), "r"(a2), "r"(a3), "r"(b0), "r"(b1));
}

// ============================================================================
// Phase 1: xk = x @ W + bias0  (tf32 tensor cores, unchanged from R12/R15)
// ============================================================================
#define GBM 128
#define GBN 64
#define GBK 32
#define ASTR 36
#define BSTR 68

__global__ void __launch_bounds__(256, 2)
gemm_xk_tf32(const float* __restrict__ A,
             const float* __restrict__ W,
             const float* __restrict__ bias)
{
    __shared__ float As[2][GBM][ASTR];
    __shared__ float Bs[2][GBK][BSTR];

    const int bm   = blockIdx.y * GBM;
    const int bn   = blockIdx.x * GBN;
    const int tid  = threadIdx.x;
    const int wid  = tid >> 5;
    const int lane = tid & 31;
    const int wm   = (wid & 3) * 32;
    const int wn   = (wid >> 2) * 32;
    const int lr   = lane >> 2;
    const int lc   = lane & 3;

    float acc[2][4][4];
#pragma unroll
    for (int mi = 0; mi < 2; mi++)
#pragma unroll
        for (int ni = 0; ni < 4; ni++)
#pragma unroll
            for (int q = 0; q < 4; q++) acc[mi][ni][q] = 0.f;

    float4 aref[4], bref[2];

#pragma unroll
    for (int i = 0; i < 4; i++) {
        int f = tid + i * 256, row = f >> 3, c4 = (f & 7) << 2;
        aref[i] = *(const float4*)&A[(size_t)(bm + row) * DD + c4];
    }
#pragma unroll
    for (int i = 0; i < 2; i++) {
        int f = tid + i * 256, k = f >> 4, n4 = (f & 15) << 2;
        bref[i] = *(const float4*)&W[(size_t)k * NC + bn + n4];
    }
#pragma unroll
    for (int i = 0; i < 4; i++) {
        int f = tid + i * 256, row = f >> 3, c4 = (f & 7) << 2;
        *(float4*)&As[0][row][c4] = aref[i];
    }
#pragma unroll
    for (int i = 0; i < 2; i++) {
        int f = tid + i * 256, k = f >> 4, n4 = (f & 15) << 2;
        *(float4*)&Bs[0][k][n4] = bref[i];
    }
    __syncthreads();

    const int NKT = DD / GBK;
    for (int kt = 0; kt < NKT; kt++) {
        const int cur = kt & 1;

        if (kt < NKT - 1) {
            int kb = (kt + 1) * GBK;
#pragma unroll
            for (int i = 0; i < 4; i++) {
                int f = tid + i * 256, row = f >> 3, c4 = (f & 7) << 2;
                aref[i] = *(const float4*)&A[(size_t)(bm + row) * DD + kb + c4];
            }
#pragma unroll
            for (int i = 0; i < 2; i++) {
                int f = tid + i * 256, k = f >> 4, n4 = (f & 15) << 2;
                bref[i] = *(const float4*)&W[(size_t)(kb + k) * NC + bn + n4];
            }
        }

#pragma unroll
        for (int k8 = 0; k8 < 4; k8++) {
            uint32_t bf[4][2];
#pragma unroll
            for (int ni = 0; ni < 4; ni++) {
                int cb = wn + ni * 8;
                bf[ni][0] = f2tf32(Bs[cur][k8 * 8 + lc    ][cb + lr]);
                bf[ni][1] = f2tf32(Bs[cur][k8 * 8 + lc + 4][cb + lr]);
            }
#pragma unroll
            for (int mi = 0; mi < 2; mi++) {
                int rb = wm + mi * 16;
                uint32_t a0 = f2tf32(As[cur][rb + lr    ][k8 * 8 + lc    ]);
                uint32_t a1 = f2tf32(As[cur][rb + lr + 8][k8 * 8 + lc    ]);
                uint32_t a2 = f2tf32(As[cur][rb + lr    ][k8 * 8 + lc + 4]);
                uint32_t a3 = f2tf32(As[cur][rb + lr + 8][k8 * 8 + lc + 4]);
#pragma unroll
                for (int ni = 0; ni < 4; ni++)
                    mma_tf32(acc[mi][ni], a0, a1, a2, a3, bf[ni][0], bf[ni][1]);
            }
        }

        if (kt < NKT - 1) {
            __syncthreads();
#pragma unroll
            for (int i = 0; i < 4; i++) {
                int f = tid + i * 256, row = f >> 3, c4 = (f & 7) << 2;
                *(float4*)&As[cur ^ 1][row][c4] = aref[i];
            }
#pragma unroll
            for (int i = 0; i < 2; i++) {
                int f = tid + i * 256, k = f >> 4, n4 = (f & 15) << 2;
                *(float4*)&Bs[cur ^ 1][k][n4] = bref[i];
            }
            __syncthreads();
        }
    }

#pragma unroll
    for (int mi = 0; mi < 2; mi++) {
#pragma unroll
        for (int ni = 0; ni < 4; ni++) {
            int r0 = bm + wm + mi * 16 + lr;
            int c0 = bn + wn + ni * 8 + lc * 2;
            float bz0 = bias[c0], bz1 = bias[c0 + 1];
            float2 v0 = make_float2(acc[mi][ni][0] + bz0, acc[mi][ni][1] + bz1);
            float2 v1 = make_float2(acc[mi][ni][2] + bz0, acc[mi][ni][3] + bz1);
            *(float2*)&g_xk[(size_t)r0 * NC + c0]       = v0;
            *(float2*)&g_xk[(size_t)(r0 + 8) * NC + c0] = v1;
        }
    }
}

// ============================================================================
// Phase 2: persistent GRU recurrence — TAGGED-WORD handoff (data==flag).
//   8 groups x 16 CTAs; CTA c owns units [32c,32c+32); thread (u=lane,
//   ks=warp) holds U[k0..k0+32) for unit u's 3 gate columns (48 f32x2 regs).
//   Handoff: producer gate thread packs {h' bits, tag=t+1} in ONE 8-byte word
//   and st.relaxed.gpu.b64's it into parity buffer g_hx[(t+1)&1]. Consumer
//   lane u of warp ks polls ITS OWN two words (batch 0/1, unit 32ks+u) with
//   ld.relaxed.gpu.b64 until both tags == t+1 — single-copy atomicity makes
//   the payload valid the instant the tag matches; no fences, no counters,
//   no release/acquire serialization, and every warp polls distinct L2 lines.
//   Safety: red[] parity double-buffered (racing consumers write red[par^1],
//   then block at the next __syncthreads). Parity-slot reuse: a tag t+3
//   overwrite requires the polling warp itself to have passed poll(t) —
//   impossible while it polls (complete consumer<->producer graph).
//   Tags monotonic within a replay; 128 KB memset resets them per replay.
// ============================================================================
__global__ void __launch_bounds__(512, 1)
gru_rec_kernel(const float* __restrict__ RK,
               const float* __restrict__ bias,
               float* __restrict__ out)
{
    __shared__ float red[2][16][32][7];    // [parity][ks][u][gate*2+b]
    __shared__ float h_chunk[16][2][32];   // per-warp private h slice
    __shared__ float rb_s[96];             // recurrent bias slice

    const int bx  = blockIdx.x;
    const int g   = bx >> 4;               // group 0..7
    const int c   = bx & 15;               // cta-in-group 0..15
    const int tid = threadIdx.x;
    const int u   = tid & 31;              // lane
    const int ks  = tid >> 5;              // warp / K-split 0..15
    const int jb  = c * 32;                // first unit owned
    const int b0  = g * 2;                 // first global batch
    const int k0  = ks * 32;               // this warp's K chunk

    // ---- Load U slice into registers ---------------------------------------
    ull ureg[3][16];
#pragma unroll
    for (int gi = 0; gi < 3; gi++)
#pragma unroll
        for (int i = 0; i < 16; i++) {
            int k = k0 + 2 * i;
            float lo = RK[(size_t)k       * NC + gi * HH + jb + u];
            float hi = RK[(size_t)(k + 1) * NC + gi * HH + jb + u];
            ureg[gi][i] = pk2(lo, hi);
        }
    if (tid < 96)
        rb_s[tid] = bias[NC + (tid >> 5) * HH + jb + (tid & 31)];
    // zero own h chunk (h0 = 0)
    for (int i = u; i < 64; i += 32) ((float*)h_chunk[ks])[i] = 0.f;
    __syncthreads();

    // consumer lane u of warp ks polls unit k0+u for both batches
    const ull* pollA0 = &g_hx[0][b0][k0 + u];        // parity-0 base, batch 0
    const ull* pollB0 = &g_hx[0][b0 + 1][k0 + u];    // parity-0 base, batch 1
    const size_t PAR_STRIDE = (size_t)BB * HH;       // ull elems between parities

    float h_old = 0.f;                     // gate threads: own h from last step

    // xk prefetch for t = 0 (gate warps only)
    float xz = 0.f, xr = 0.f, xh = 0.f;
    size_t xbase0 = 0;
    if (ks < 2) {
        xbase0 = ((size_t)(b0 + ks) * TT) * NC + jb + u;
        xz = g_xk[xbase0];
        xr = g_xk[xbase0 + HH];
        xh = g_xk[xbase0 + 2 * HH];
    }

    for (int t = 0; t < TT; t++) {
        const int par = t & 1;

        // ---- packed dot over own 32-wide K chunk ---------------------------
        const ull* hp0 = (const ull*)h_chunk[ks][0];
        const ull* hp1 = (const ull*)h_chunk[ks][1];
        ull a0 = 0, a1 = 0, a2 = 0, a3 = 0, a4 = 0, a5 = 0;
#pragma unroll
        for (int i = 0; i < 16; i++) {
            ull h0 = hp0[i];               // broadcast LDS.64
            ull h1 = hp1[i];
            a0 = fma2(ureg[0][i], h0, a0);
            a1 = fma2(ureg[1][i], h0, a1);
            a2 = fma2(ureg[2][i], h0, a2);
            a3 = fma2(ureg[0][i], h1, a3);
            a4 = fma2(ureg[1][i], h1, a4);
            a5 = fma2(ureg[2][i], h1, a5);
        }
        {
            float lo, hi;
            unpk2(lo, hi, a0); red[par][ks][u][0] = lo + hi;   // z, b0
            unpk2(lo, hi, a1); red[par][ks][u][2] = lo + hi;   // r, b0
            unpk2(lo, hi, a2); red[par][ks][u][4] = lo + hi;   // h, b0
            unpk2(lo, hi, a3); red[par][ks][u][1] = lo + hi;   // z, b1
            unpk2(lo, hi, a4); red[par][ks][u][3] = lo + hi;   // r, b1
            unpk2(lo, hi, a5); red[par][ks][u][5] = lo + hi;   // h, b1
        }
        __syncthreads();

        // ---- gate warps: reduce + gates + tagged publish -------------------
        if (ks < 2) {
            float s0 = 0.f, s1 = 0.f, s2 = 0.f;
#pragma unroll
            for (int q = 0; q < 16; q++) {
                s0 += red[par][q][u][0 + ks];
                s1 += red[par][q][u][2 + ks];
                s2 += red[par][q][u][4 + ks];
            }
            s0 += rb_s[u];
            s1 += rb_s[32 + u];
            s2 += rb_s[64 + u];

            float z    = sigmoid_f(xz + s0);
            float r    = sigmoid_f(xr + s1);
            float cand = tanh_f(xh + r * s2);
            float hn   = z * h_old + (1.f - z) * cand;
            h_old = hn;

            int gb = b0 + ks;
            // tagged word: {tag = t+1 (hi32), h' bits (lo32)} — one atom.
            {
                ull w = ((ull)(uint32_t)(t + 1) << 32) |
                        (ull)__float_as_uint(hn);
                asm volatile("st.relaxed.gpu.global.b64 [%0], %1;"
                             :: "l"(&g_hx[(t + 1) & 1][gb][jb + u]), "l"(w)
                             : "memory");
            }
            out[((size_t)gb * TT + t) * HH + jb + u] = hn;
            if (t == TT - 1)
                out[(size_t)BB * TT * HH + (size_t)gb * HH + jb + u] = hn;

            // prefetch next step's xk (consumed next iteration)
            {
                size_t nb = xbase0 + (size_t)((t + 1 < TT) ? t + 1 : t) * NC;
                xz = g_xk[nb];
                xr = g_xk[nb + HH];
                xh = g_xk[nb + 2 * HH];
            }
        }

        // ---- poll own tagged words (per-source wavefront, no counters) -----
        {
            const ull* pa = pollA0 + ((t + 1) & 1) * PAR_STRIDE;
            const ull* pb = pollB0 + ((t + 1) & 1) * PAR_STRIDE;
            const uint32_t want = (uint32_t)(t + 1);
            ull wa, wb;
            uint32_t ta, tb;
            do {
                asm volatile("ld.relaxed.gpu.global.b64 %0, [%1];"
                             : "=l"(wa) : "l"(pa) : "memory");
                asm volatile("ld.relaxed.gpu.global.b64 %0, [%1];"
                             : "=l"(wb) : "l"(pb) : "memory");
                ta = (uint32_t)(wa >> 32);
                tb = (uint32_t)(wb >> 32);
            } while (ta != want || tb != want);
            h_chunk[ks][0][u] = __uint_as_float((uint32_t)wa);
            h_chunk[ks][1][u] = __uint_as_float((uint32_t)wb);
        }
        __syncwarp();
    }
}

// ============================================================================
extern "C" void kernel_launch(void* const* d_in, const int* in_sizes, int n_in,
                              void* d_out, int out_size)
{
    const float* x    = (const float*)d_in[0];   // [16,4096,512]
    const float* Wk   = (const float*)d_in[1];   // [512,1536]
    const float* RK   = (const float*)d_in[2];   // [512,1536]
    const float* bias = (const float*)d_in[3];   // [2,1536]
    float* out = (float*)d_out;                  // outputs ++ state

    // Reset the tagged words (tags monotonic within a replay; 128 KB memset).
    void* hx_ptr = nullptr;
    cudaGetSymbolAddress(&hx_ptr, g_hx);
    cudaMemsetAsync(hx_ptr, 0, sizeof(ull) * 2 * BB * HH);

    // Phase 1: input projection GEMM (tf32 tensor cores).
    dim3 grid1(NC / GBN, (BB * TT) / GBM);
    gemm_xk_tf32<<<grid1, 256>>>(x, Wk, bias);

    // Phase 2: persistent recurrence (tagged-word handoff).
    gru_rec_kernel<<<128, 512>>>(RK, bias, out);
}